// round 7
// baseline (speedup 1.0000x reference)
#include <cuda_runtime.h>

// Shape (B=2, C=1, D=160, H=192, W=224), win=5, eps=1e-8
#define DD 160
#define HH 192
#define WW 224
#define BB 2
#define HW (HH * WW)
#define TX 32
#define TY 12
#define RR 16                    // rows per block = TY + 4
#define RCOLS 36                 // halo cols = TX + 4
#define CHUNK 40                 // z-outputs per block
#define GX (WW / TX)             // 7
#define GY (HH / TY)             // 16
#define NCZ (DD / CHUNK)         // 4
#define GZ (BB * NCZ)            // 8
#define NBLOCKS (GX * GY * GZ)   // 896
#define NT 512
#define NTOT ((double)BB * DD * HH * WW)

__device__ double g_partials[NBLOCKS];
__device__ unsigned int g_count = 0;

// 5-tap sliding sum along lanes within 16-lane segments (valid for seg-lane 0..11)
#define SLIDE5(OUT, Q) do {                                                     \
    float t1_ = (Q) + __shfl_down_sync(0xffffffffu, (Q), 1, 16);                \
    float t2_ = t1_ + __shfl_down_sync(0xffffffffu, t1_, 2, 16);                \
    OUT = t2_ + __shfl_down_sync(0xffffffffu, (Q), 4, 16);                      \
} while (0)

// x-box + z-ring + (optional) y-shuffle + emit, for slice S of pair PAR.
#define XRS(SLOT, S, PAR, DOY) do {                                             \
    float2 v0 = sIJ[PAR][S][ecol    ][erow];                                    \
    float2 v1 = sIJ[PAR][S][ecol + 1][erow];                                    \
    float2 v2 = sIJ[PAR][S][ecol + 2][erow];                                    \
    float2 v3 = sIJ[PAR][S][ecol + 3][erow];                                    \
    float2 v4 = sIJ[PAR][S][ecol + 4][erow];                                    \
    const float a0 = v0.x + v1.x + v2.x + v3.x + v4.x;                          \
    const float a1 = v0.y + v1.y + v2.y + v3.y + v4.y;                          \
    const float a2 = fmaf(v4.x, v4.x, fmaf(v3.x, v3.x,                          \
                     fmaf(v2.x, v2.x, fmaf(v1.x, v1.x, v0.x * v0.x))));         \
    const float a3 = fmaf(v4.y, v4.y, fmaf(v3.y, v3.y,                          \
                     fmaf(v2.y, v2.y, fmaf(v1.y, v1.y, v0.y * v0.y))));         \
    const float a4 = fmaf(v4.x, v4.y, fmaf(v3.x, v3.y,                          \
                     fmaf(v2.x, v2.y, fmaf(v1.x, v1.y, v0.x * v0.y))));         \
    SI  += a0 - r0[SLOT]; r0[SLOT] = a0;                                        \
    SJ  += a1 - r1[SLOT]; r1[SLOT] = a1;                                        \
    SII += a2 - r2[SLOT]; r2[SLOT] = a2;                                        \
    SJJ += a3 - r3[SLOT]; r3[SLOT] = a3;                                        \
    SIJ += a4 - r4[SLOT]; r4[SLOT] = a4;                                        \
    if (DOY) {                                                                  \
        float yI, yJ, yII, yJJ, yIJ;                                            \
        SLIDE5(yI,  SI);  SLIDE5(yJ,  SJ);  SLIDE5(yII, SII);                   \
        SLIDE5(yJJ, SJJ); SLIDE5(yIJ, SIJ);                                     \
        if (emit_row) {                                                         \
            const float w = sW[PAR][S][erow][ecol];                             \
            const float wsz = 125.0f, inv = 1.0f / 125.0f;                      \
            const float uI = yI * inv, uJ = yJ * inv;                           \
            const float cross = yIJ - uJ * yI - uI * yJ + uI * uJ * wsz;        \
            const float Iv = yII - 2.0f * uI * yI + uI * uI * wsz;              \
            const float Jv = yJJ - 2.0f * uJ * yJ + uJ * uJ * wsz;              \
            const float cc = (cross * cross) / (Iv * Jv + 1e-8f);               \
            acc = fmaf(cc, w, acc);                                             \
        }                                                                       \
    }                                                                           \
} while (0)

// One phase = two z-slices, one barrier. All args compile-time literals.
#define PHASE(SA, SB, PAR, DOY, DOW) do {                                       \
    float Ai0 = 0.f, Aj0 = 0.f, Ai1 = 0.f, Aj1 = 0.f;                           \
    float Bi0 = 0.f, Bj0 = 0.f, Bi1 = 0.f, Bj1 = 0.f;                           \
    {                                                                           \
        const bool zA = (zpre < DD), zB = (zpre + 1 < DD);                      \
        if (zA && ok0) { const int g = pB0 + preoff;      Ai0 = gI[g]; Aj0 = gJ[g]; } \
        if (zB && ok0) { const int g = pB0 + preoff + HW; Bi0 = gI[g]; Bj0 = gJ[g]; } \
        if (has1) {                                                             \
            if (zA && ok1) { const int g = pB1 + preoff;      Ai1 = gI[g]; Aj1 = gJ[g]; } \
            if (zB && ok1) { const int g = pB1 + preoff + HW; Bi1 = gI[g]; Bj1 = gJ[g]; } \
        }                                                                       \
    }                                                                           \
    float wA = 0.f, wB = 0.f;                                                   \
    if (DOW && wok) {                                                           \
        const int zw = zpre - 2;                                                \
        if (zw < DD)     wA = gW[wbase + zw * HW];                              \
        if (zw + 1 < DD) wB = gW[wbase + (zw + 1) * HW];                        \
    }                                                                           \
    XRS(SA, 0, PAR, DOY);                                                       \
    XRS(SB, 1, PAR, DOY);                                                       \
    sIJ[(PAR) ^ 1][0][col0][row0] = make_float2(Ai0, Aj0);                      \
    sIJ[(PAR) ^ 1][1][col0][row0] = make_float2(Bi0, Bj0);                      \
    if (has1) {                                                                 \
        sIJ[(PAR) ^ 1][0][col1][row1] = make_float2(Ai1, Aj1);                  \
        sIJ[(PAR) ^ 1][1][col1][row1] = make_float2(Bi1, Bj1);                  \
    }                                                                           \
    if (DOW && wok) {                                                           \
        sW[(PAR) ^ 1][0][wr][wc] = wA;                                          \
        sW[(PAR) ^ 1][1][wr][wc] = wB;                                          \
    }                                                                           \
    __syncthreads();                                                            \
    zpre += 2; preoff += 2 * HW;                                                \
} while (0)

__global__ __launch_bounds__(NT, 2)
void ncc_fused(const float* __restrict__ gI,
               const float* __restrict__ gJ,
               const float* __restrict__ gW,
               float* __restrict__ out)
{
    // raw (I,J) tile, TRANSPOSED: [pair][slice][col][row] with row-pad 17
    __shared__ float2 sIJ[2][2][RCOLS][RR + 1];   // 19584 B
    // weight stage: [pair][slice][out_row 12][out_col 32+pad]
    __shared__ float  sW[2][2][TY][TX + 1];       // 6336 B
    __shared__ double sred[16];
    __shared__ int    slast;

    const int tid  = threadIdx.x;
    const int lane = tid & 31;
    const int warp = tid >> 5;
    const int x0 = blockIdx.x * TX;
    const int y0 = blockIdx.y * TY;
    const int cz = blockIdx.z % NCZ;
    const int b  = blockIdx.z / NCZ;
    const int z0 = cz * CHUNK;
    const int base = b * (DD * HW);

    // ---- raw loader mapping: 576 entries (row-major for coalescing) ----
    const int row0 = tid / RCOLS, col0 = tid - row0 * RCOLS;
    const int gy0 = y0 + row0 - 2, gx0 = x0 + col0 - 2;
    const bool ok0 = ((unsigned)gy0 < HH) && ((unsigned)gx0 < WW);
    const int pB0 = base + (ok0 ? gy0 * WW + gx0 : 0);

    const bool has1 = (tid < RR * RCOLS - NT);    // 64 extra entries
    const int e1 = tid + NT;
    const int row1 = e1 / RCOLS, col1 = e1 - row1 * RCOLS;
    const int gy1 = y0 + row1 - 2, gx1 = x0 + col1 - 2;
    const bool ok1 = ((unsigned)gy1 < HH) && ((unsigned)gx1 < WW);
    const int pB1 = base + (ok1 ? gy1 * WW + gx1 : 0);

    // ---- W loader mapping: 384 entries (coalesced), exact output region ----
    const bool wok = (tid < TY * TX);
    const int wr = tid >> 5, wc = tid & 31;       // out row 0..11, col 0..31
    const int wbase = base + (y0 + wr) * WW + (x0 + wc);

    // ---- XR/emit mapping: warp owns 2 cols x 16 rows; lane = row (mod 16) ----
    const int ecol = (warp << 1) + (lane >> 4);   // output col 0..31
    const int erow = lane & 15;                   // row 0..15
    const bool emit_row = (erow < TY);            // rows 0..11 emit

    // ---- z ring (static slots) + running sums ----
    float r0[5] = {0,0,0,0,0}, r1[5] = {0,0,0,0,0}, r2[5] = {0,0,0,0,0};
    float r3[5] = {0,0,0,0,0}, r4[5] = {0,0,0,0,0};
    float SI = 0.f, SJ = 0.f, SII = 0.f, SJJ = 0.f, SIJ = 0.f;
    float acc = 0.f;

    // ---- prologue: slices z0-2, z0-1 into pair 0 ----
    {
        const int zp = z0 - 2;
        const int zo = zp * HW;
        float a0i = 0.f, a0j = 0.f, b0i = 0.f, b0j = 0.f;
        float a1i = 0.f, a1j = 0.f, b1i = 0.f, b1j = 0.f;
        if (zp >= 0 && ok0)     { const int g = pB0 + zo;      a0i = gI[g]; a0j = gJ[g]; }
        if (zp + 1 >= 0 && ok0) { const int g = pB0 + zo + HW; b0i = gI[g]; b0j = gJ[g]; }
        if (has1) {
            if (zp >= 0 && ok1)     { const int g = pB1 + zo;      a1i = gI[g]; a1j = gJ[g]; }
            if (zp + 1 >= 0 && ok1) { const int g = pB1 + zo + HW; b1i = gI[g]; b1j = gJ[g]; }
        }
        sIJ[0][0][col0][row0] = make_float2(a0i, a0j);
        sIJ[0][1][col0][row0] = make_float2(b0i, b0j);
        if (has1) {
            sIJ[0][0][col1][row1] = make_float2(a1i, a1j);
            sIJ[0][1][col1][row1] = make_float2(b1i, b1j);
        }
        __syncthreads();
    }

    int zpre = z0;               // phase p prefetches slices z0+2p, z0+2p+1
    int preoff = z0 * HW;

    PHASE(0, 1, 0, false, false);      // p0: XR z0-2, z0-1
    PHASE(2, 3, 1, false, true );      // p1: XR z0,   z0+1 ; preload W z0, z0+1
#pragma unroll 1
    for (int g = 0; g < 2; ++g) {      // p2..p21 (slot period 5 x parity 2 = 10)
        PHASE(4, 0, 0, true, true);
        PHASE(1, 2, 1, true, true);
        PHASE(3, 4, 0, true, true);
        PHASE(0, 1, 1, true, true);
        PHASE(2, 3, 0, true, true);
        PHASE(4, 0, 1, true, true);
        PHASE(1, 2, 0, true, true);
        PHASE(3, 4, 1, true, true);
        PHASE(0, 1, 0, true, true);
        PHASE(2, 3, 1, true, true);
    }

    // ---- reduction: shuffle tree (deterministic) ----
    double a = (double)acc;
#pragma unroll
    for (int off = 16; off > 0; off >>= 1)
        a += __shfl_down_sync(0xffffffffu, a, off);
    if (lane == 0) sred[warp] = a;
    __syncthreads();
    if (warp == 0) {
        double s = (lane < 16) ? sred[lane] : 0.0;
#pragma unroll
        for (int off = 8; off > 0; off >>= 1)
            s += __shfl_down_sync(0xffffffffu, s, off);
        if (lane == 0) {
            const int bidx = ((int)blockIdx.z * GY + (int)blockIdx.y) * GX + (int)blockIdx.x;
            g_partials[bidx] = s;
            __threadfence();
            const unsigned v = atomicAdd(&g_count, 1u);
            slast = (v == NBLOCKS - 1);
        }
    }
    __syncthreads();

    // ---- last block folds all partials in fixed order ----
    if (slast) {
        double s = 0.0;
        for (int i = tid; i < NBLOCKS; i += NT) s += g_partials[i];
#pragma unroll
        for (int off = 16; off > 0; off >>= 1)
            s += __shfl_down_sync(0xffffffffu, s, off);
        if (lane == 0) sred[warp] = s;
        __syncthreads();
        if (warp == 0) {
            double t = (lane < 16) ? sred[lane] : 0.0;
#pragma unroll
            for (int off = 8; off > 0; off >>= 1)
                t += __shfl_down_sync(0xffffffffu, t, off);
            if (lane == 0) {
                out[0] = (float)(-t / NTOT);
                g_count = 0;   // reset for next graph replay
            }
        }
    }
}

extern "C" void kernel_launch(void* const* d_in, const int* in_sizes, int n_in,
                              void* d_out, int out_size)
{
    const float* I  = (const float*)d_in[0];
    const float* J  = (const float*)d_in[1];
    const float* Wt = (const float*)d_in[2];
    float* out = (float*)d_out;

    dim3 grid(GX, GY, GZ);
    ncc_fused<<<grid, NT>>>(I, J, Wt, out);
}